// round 15
// baseline (speedup 1.0000x reference)
#include <cuda_runtime.h>
#include <cuda_bf16.h>
#include <math.h>

// HyperbolicMLR via HMMA (mma.sync m16n8k16 bf16, fp32 acc), hi/lo error split.
// B rows interleaved (2c=p_poin, 2c+1=a_poin) -> acc pairs are (dotp, dota).
// CTA: 128 batch x 32 classes, 8 warps (warp tile 32m x 32n). 3 CTAs/SM.

#define K_CURV 0.1f
#define SQRT_K 0.31622776601683794f

typedef unsigned int u32;

#define LDB   144                    // padded row stride bytes (72 halves)
#define SB_AH 0                      // A hi: 128 x 144B
#define SB_AL 18432                  // A lo
#define SB_BH 36864                  // B hi: 64 rows (2c=p, 2c+1=a)
#define SB_BL 46080                  // B lo
#define SB_X2 55296                  // |p_poin|^2      [32] f32
#define SB_PC 55424                  // dot(mp,a_poin)  [32]
#define SB_SC 55552                  // scale           [32]
#define SB_CF 55680                  // 2*sqrt_k/a_norm [32]
#define SB_Y2 55808                  // |x_b|^2         [128]
#define SB_TOTAL (SB_Y2 + 512)

static __device__ __forceinline__ u32 smem_u32(const void* p) {
    u32 a;
    asm("{ .reg .u64 t; cvta.to.shared.u64 t, %1; cvt.u32.u64 %0, t; }" : "=r"(a) : "l"(p));
    return a;
}
static __device__ __forceinline__ void ldm_x4(u32* r, u32 addr) {
    asm volatile("ldmatrix.sync.aligned.m8n8.x4.shared.b16 {%0,%1,%2,%3}, [%4];"
                 : "=r"(r[0]), "=r"(r[1]), "=r"(r[2]), "=r"(r[3]) : "r"(addr));
}
static __device__ __forceinline__ void ldm_x2(u32* r, u32 addr) {
    asm volatile("ldmatrix.sync.aligned.m8n8.x2.shared.b16 {%0,%1}, [%2];"
                 : "=r"(r[0]), "=r"(r[1]) : "r"(addr));
}
static __device__ __forceinline__ void mma16816(float* c, const u32* a, const u32* b) {
    asm volatile("mma.sync.aligned.m16n8k16.row.col.f32.bf16.bf16.f32 "
                 "{%0,%1,%2,%3}, {%4,%5,%6,%7}, {%8,%9}, {%0,%1,%2,%3};"
                 : "+f"(c[0]), "+f"(c[1]), "+f"(c[2]), "+f"(c[3])
                 : "r"(a[0]), "r"(a[1]), "r"(a[2]), "r"(a[3]), "r"(b[0]), "r"(b[1]));
}
static __device__ __forceinline__ float rcp_a(float x)  { float r; asm("rcp.approx.f32 %0, %1;"  : "=f"(r) : "f"(x)); return r; }
static __device__ __forceinline__ float sqrt_a(float x) { float r; asm("sqrt.approx.f32 %0, %1;" : "=f"(r) : "f"(x)); return r; }
static __device__ __forceinline__ float lg2_a(float x)  { float r; asm("lg2.approx.f32 %0, %1;"  : "=f"(r) : "f"(x)); return r; }

static __device__ __forceinline__ u32 hilo_hi2(float a, float b, float& ra, float& rb) {
    __nv_bfloat16 ha = __float2bfloat16_rn(a);
    __nv_bfloat16 hb = __float2bfloat16_rn(b);
    ra = a - __bfloat162float(ha);
    rb = b - __bfloat162float(hb);
    return (u32)__bfloat16_as_ushort(ha) | ((u32)__bfloat16_as_ushort(hb) << 16);
}
static __device__ __forceinline__ u32 bf2(float a, float b) {
    return (u32)__bfloat16_as_ushort(__float2bfloat16_rn(a))
         | ((u32)__bfloat16_as_ushort(__float2bfloat16_rn(b)) << 16);
}

__global__ void __launch_bounds__(256, 3)
hmlr_hmma(const float* __restrict__ x,
          const float* __restrict__ a_vals,
          const float* __restrict__ p_vals,
          float* __restrict__ out, int B, int C) {
    extern __shared__ __align__(16) char sm[];
    float* s_x2 = (float*)(sm + SB_X2);
    float* s_pc = (float*)(sm + SB_PC);
    float* s_sc = (float*)(sm + SB_SC);
    float* s_cf = (float*)(sm + SB_CF);
    float* s_y2 = (float*)(sm + SB_Y2);
    const u32 sb = smem_u32(sm);

    const int tid   = threadIdx.x;
    const int lane  = tid & 31;
    const int w     = tid >> 5;
    const int cBase = blockIdx.x * 32;
    const int bBase = blockIdx.y * 128;

    // ===== phase 1a: x rows -> A hi/lo + y2 (2 threads per row) ================
    {
        const int r = tid >> 1;
        const int h = tid & 1;
        const float4* xr = (const float4*)(x + (size_t)(bBase + r) * 64 + h * 32);
        float v[32]; float s = 0.f;
#pragma unroll
        for (int i = 0; i < 8; ++i) {
            float4 q = xr[i];
            v[4*i+0]=q.x; v[4*i+1]=q.y; v[4*i+2]=q.z; v[4*i+3]=q.w;
            s += q.x*q.x + q.y*q.y + q.z*q.z + q.w*q.w;
        }
        s += __shfl_xor_sync(0xffffffffu, s, 1);
        if (h == 0) s_y2[r] = s;
        char* rowH = sm + SB_AH + r * LDB + h * 64;
        char* rowL = sm + SB_AL + r * LDB + h * 64;
#pragma unroll
        for (int i = 0; i < 16; ++i) {
            float la, lb;
            u32 hh = hilo_hi2(v[2*i], v[2*i+1], la, lb);
            *(u32*)(rowH + 4*i) = hh;
            *(u32*)(rowL + 4*i) = bf2(la, lb);
        }
    }

    // ===== phase 1b: class prep (8 threads per class, 8 d's each) ==============
    {
        const int cl = tid >> 3;                 // local class 0..31
        const int sq = tid & 7;                  // d in [sq*8, +8)
        const int cc = cBase + cl;
        const bool valid = (cc < C);

        float P[8], A[8];
        if (valid) {
            const float4* pb4 = (const float4*)(p_vals + (size_t)cc * 64 + sq * 8);
            const float4* ab4 = (const float4*)(a_vals + (size_t)cc * 64 + sq * 8);
#pragma unroll
            for (int i = 0; i < 2; ++i) {
                float4 pv = pb4[i], av = ab4[i];
                P[4*i+0]=pv.x; P[4*i+1]=pv.y; P[4*i+2]=pv.z; P[4*i+3]=pv.w;
                A[4*i+0]=av.x; A[4*i+1]=av.y; A[4*i+2]=av.z; A[4*i+3]=av.w;
            }
        } else {
#pragma unroll
            for (int i = 0; i < 8; ++i) { P[i] = 0.f; A[i] = 0.f; }
        }

        float psq = 0.f;
#pragma unroll
        for (int i = 0; i < 8; ++i) psq += P[i] * P[i];
        psq += __shfl_xor_sync(0xffffffffu, psq, 1);
        psq += __shfl_xor_sync(0xffffffffu, psq, 2);
        psq += __shfl_xor_sync(0xffffffffu, psq, 4);

        float pn  = fmaxf(sqrtf(psq), 1e-15f);
        float arg = SQRT_K * pn;
        float t   = tanhf(arg) / arg;            // exp0 factor
        float p2  = t * t * psq;                 // |p_poin|^2
        float fac = 1.f + K_CURV * p2;

        float a2 = 0.f, pad = 0.f;
#pragma unroll
        for (int i = 0; i < 8; ++i) {
            float pp = t * P[i];
            float ap = fac * A[i];
            P[i] = pp; A[i] = ap;
            a2  += ap * ap;
            pad += pp * ap;
        }
        a2  += __shfl_xor_sync(0xffffffffu, a2, 1);
        a2  += __shfl_xor_sync(0xffffffffu, a2, 2);
        a2  += __shfl_xor_sync(0xffffffffu, a2, 4);
        pad += __shfl_xor_sync(0xffffffffu, pad, 1);
        pad += __shfl_xor_sync(0xffffffffu, pad, 2);
        pad += __shfl_xor_sync(0xffffffffu, pad, 4);

        if (sq == 0) {
            float an  = fmaxf(sqrtf(a2), 1e-15f);
            float lam = 2.f / (1.f - K_CURV * p2);
            s_x2[cl] = p2;
            s_pc[cl] = -pad;                     // dot(mp, a_poin)
            s_sc[cl] = lam * an / SQRT_K;        // scale
            s_cf[cl] = 2.f * SQRT_K / an;        // folded consts
        }
        char* pH = sm + SB_BH + (2*cl)   * LDB + sq * 16;
        char* pL = sm + SB_BL + (2*cl)   * LDB + sq * 16;
        char* aH = sm + SB_BH + (2*cl+1) * LDB + sq * 16;
        char* aL = sm + SB_BL + (2*cl+1) * LDB + sq * 16;
#pragma unroll
        for (int i = 0; i < 4; ++i) {
            float la, lb;
            u32 hh = hilo_hi2(P[2*i], P[2*i+1], la, lb);
            *(u32*)(pH + 4*i) = hh;
            *(u32*)(pL + 4*i) = bf2(la, lb);
            hh = hilo_hi2(A[2*i], A[2*i+1], la, lb);
            *(u32*)(aH + 4*i) = hh;
            *(u32*)(aL + 4*i) = bf2(la, lb);
        }
    }
    __syncthreads();

    // ===== phase 2: HMMA mainloop. Warp tile 32m x 32n, K=64 ===================
    const int m0  = (w & 3) * 32;
    const int n0r = (w >> 2) * 32;               // B row offset (32 rows = 16 classes)
    const int l16 = lane & 15;

    const u32 aoff0 = (u32)((m0      + l16) * LDB + (lane >> 4) * 16);
    const u32 aoff1 = (u32)((m0 + 16 + l16) * LDB + (lane >> 4) * 16);
    const u32 boff  = (u32)((n0r + (l16 & 7)) * LDB + ((l16 >> 3) & 1) * 16);

    float acc[2][4][4];
#pragma unroll
    for (int ma = 0; ma < 2; ++ma)
#pragma unroll
        for (int nb = 0; nb < 4; ++nb)
#pragma unroll
            for (int q = 0; q < 4; ++q) acc[ma][nb][q] = 0.f;

#pragma unroll
    for (int kk = 0; kk < 4; ++kk) {
        const u32 kb = kk * 32;
        u32 ah0[4], ah1[4], al0[4], al1[4];
        ldm_x4(ah0, sb + SB_AH + aoff0 + kb);
        ldm_x4(ah1, sb + SB_AH + aoff1 + kb);
        ldm_x4(al0, sb + SB_AL + aoff0 + kb);
        ldm_x4(al1, sb + SB_AL + aoff1 + kb);
#pragma unroll
        for (int nb = 0; nb < 4; ++nb) {
            u32 bh[2], bl[2];
            ldm_x2(bh, sb + SB_BH + boff + nb * (8 * LDB) + kb);
            ldm_x2(bl, sb + SB_BL + boff + nb * (8 * LDB) + kb);
            mma16816(acc[0][nb], ah0, bh);
            mma16816(acc[1][nb], ah1, bh);
            mma16816(acc[0][nb], al0, bh);
            mma16816(acc[1][nb], al1, bh);
            mma16816(acc[0][nb], ah0, bl);
            mma16816(acc[1][nb], ah1, bl);
        }
    }

    // ===== phase 3: epilogue (register-local (dotp,dota) pairs) ================
    const int tg  = lane & 3;
    const int gid = lane >> 2;
#pragma unroll
    for (int nb = 0; nb < 4; ++nb) {
        const int cl = (n0r >> 1) + nb * 4 + tg; // local class 0..31
        const int cg = cBase + cl;
        const float x2c = s_x2[cl];
        const float pcc = s_pc[cl];
        const float scc = s_sc[cl];
        const float cfc = s_cf[cl];
        const float Bf  = 1.f - K_CURV * x2c;
#pragma unroll
        for (int ma = 0; ma < 2; ++ma) {
#pragma unroll
            for (int h = 0; h < 2; ++h) {
                const int m  = m0 + ma * 16 + gid + h * 8;
                const float y2 = s_y2[m];
                const float dotp = acc[ma][nb][2*h];
                const float dota = acc[ma][nb][2*h+1];
                float xy   = -dotp;
                float base = fmaf(2.f * K_CURV, xy, 1.f);
                float Af   = fmaf(K_CURV, y2, base);
                float den  = fmaf((K_CURV * K_CURV) * x2c, y2, base);
                float dotnum = fmaf(Af, pcc, Bf * dota);
                float num  = fmaf(Af, fmaf(Af, x2c, 2.f * Bf * xy), Bf * Bf * y2);
                float wv   = fmaf(den, den, -K_CURV * num);
                float ratio = cfc * dotnum * den * rcp_a(wv);
                float tt = fabsf(ratio);
                float z  = lg2_a(tt + sqrt_a(fmaf(tt, tt, 1.f))) * 0.69314718056f;
                float rv = scc * copysignf(z, ratio);
                if (cg < C) out[(size_t)(bBase + m) * C + cg] = rv;
            }
        }
    }
}

// ===================== launch ==================================================
extern "C" void kernel_launch(void* const* d_in, const int* in_sizes, int n_in,
                              void* d_out, int out_size) {
    const float* x = (const float*)d_in[0];
    const float* a = (const float*)d_in[1];
    const float* p = (const float*)d_in[2];
    float* out = (float*)d_out;
    const int B = in_sizes[0] / 64;   // 2048
    const int C = in_sizes[1] / 64;   // 1000

    cudaFuncSetAttribute(hmlr_hmma, cudaFuncAttributeMaxDynamicSharedMemorySize, SB_TOTAL);
    dim3 grid((C + 31) / 32, B / 128);   // 32 x 16 = 512 CTAs, 3/SM
    hmlr_hmma<<<grid, 256, SB_TOTAL>>>(x, a, p, out, B, C);
}

// round 16
// speedup vs baseline: 1.0363x; 1.0363x over previous
#include <cuda_runtime.h>
#include <cuda_bf16.h>
#include <math.h>

// HyperbolicMLR, two-kernel: prep materializes bf16 hi/lo smem-images in gmem
// (deduplicating all conversion/tanh work); main = copy->ldmatrix->HMMA->epilogue.
// HMMA m16n8k16 bf16 fp32-acc, 3-term error split (AhBh + AlBh + AhBl).
// B rows interleaved (2c=p_poin, 2c+1=a_poin) -> acc pairs are (dotp, dota).
// Main CTA: 128 batch x 32 classes, 8 warps (32m x 32n each), 3 CTAs/SM.

#define K_CURV 0.1f
#define SQRT_K 0.31622776601683794f

typedef unsigned int u32;

#define LDB     144                  // padded row stride bytes (72 halves)
#define AIMG_SZ (128 * LDB * 2)      // 36864 B: hi rows then lo rows
#define BIMG_SZ (64 * LDB * 2)       // 18432 B: hi rows then lo rows

// ---- gmem scratch (allocation-free) ----
__device__ __align__(16) static char  g_Aimg[16 * AIMG_SZ];   // per batch-tile
__device__ __align__(16) static char  g_Bimg[32 * BIMG_SZ];   // per class-tile
__device__ static float g_x2[1024], g_pc[1024], g_sc[1024], g_cf[1024];
__device__ static float g_y2[2048];

// ---- main-kernel smem layout (bytes) ----
#define SB_AH 0                      // 128 x 144
#define SB_AL 18432
#define SB_BH 36864                  // 64 x 144
#define SB_BL 46080
#define SB_X2 55296                  // [32] f32
#define SB_PC 55424
#define SB_SC 55552
#define SB_CF 55680
#define SB_Y2 55808                  // [128]
#define SB_TOTAL (SB_Y2 + 512)

static __device__ __forceinline__ u32 smem_u32(const void* p) {
    u32 a;
    asm("{ .reg .u64 t; cvta.to.shared.u64 t, %1; cvt.u32.u64 %0, t; }" : "=r"(a) : "l"(p));
    return a;
}
static __device__ __forceinline__ void ldm_x4(u32* r, u32 addr) {
    asm volatile("ldmatrix.sync.aligned.m8n8.x4.shared.b16 {%0,%1,%2,%3}, [%4];"
                 : "=r"(r[0]), "=r"(r[1]), "=r"(r[2]), "=r"(r[3]) : "r"(addr));
}
static __device__ __forceinline__ void mma16816(float* c, const u32* a, const u32* b) {
    asm volatile("mma.sync.aligned.m16n8k16.row.col.f32.bf16.bf16.f32 "
                 "{%0,%1,%2,%3}, {%4,%5,%6,%7}, {%8,%9}, {%0,%1,%2,%3};"
                 : "+f"(c[0]), "+f"(c[1]), "+f"(c[2]), "+f"(c[3])
                 : "r"(a[0]), "r"(a[1]), "r"(a[2]), "r"(a[3]), "r"(b[0]), "r"(b[1]));
}
static __device__ __forceinline__ float rcp_a(float x)  { float r; asm("rcp.approx.f32 %0, %1;"  : "=f"(r) : "f"(x)); return r; }
static __device__ __forceinline__ float sqrt_a(float x) { float r; asm("sqrt.approx.f32 %0, %1;" : "=f"(r) : "f"(x)); return r; }
static __device__ __forceinline__ float lg2_a(float x)  { float r; asm("lg2.approx.f32 %0, %1;"  : "=f"(r) : "f"(x)); return r; }

static __device__ __forceinline__ u32 hilo_hi2(float a, float b, float& ra, float& rb) {
    __nv_bfloat16 ha = __float2bfloat16_rn(a);
    __nv_bfloat16 hb = __float2bfloat16_rn(b);
    ra = a - __bfloat162float(ha);
    rb = b - __bfloat162float(hb);
    return (u32)__bfloat16_as_ushort(ha) | ((u32)__bfloat16_as_ushort(hb) << 16);
}
static __device__ __forceinline__ u32 bf2(float a, float b) {
    return (u32)__bfloat16_as_ushort(__float2bfloat16_rn(a))
         | ((u32)__bfloat16_as_ushort(__float2bfloat16_rn(b)) << 16);
}

// ===================== prep: build images + scalars once =======================
__global__ void __launch_bounds__(256)
hmlr_prep(const float* __restrict__ x,
          const float* __restrict__ a_vals,
          const float* __restrict__ p_vals, int B, int C) {
    const int bx  = blockIdx.x;
    const int tid = threadIdx.x;

    if (bx < 16) {
        // ---- x rows -> A image hi/lo + y2 (2 threads per row) ----
        const int rl = tid >> 1;                 // local row 0..127
        const int h  = tid & 1;
        const int r  = bx * 128 + rl;
        const float4* xr = (const float4*)(x + (size_t)r * 64 + h * 32);
        float v[32]; float s = 0.f;
#pragma unroll
        for (int i = 0; i < 8; ++i) {
            float4 q = xr[i];
            v[4*i+0]=q.x; v[4*i+1]=q.y; v[4*i+2]=q.z; v[4*i+3]=q.w;
            s += q.x*q.x + q.y*q.y + q.z*q.z + q.w*q.w;
        }
        s += __shfl_xor_sync(0xffffffffu, s, 1);
        if (h == 0) g_y2[r] = s;
        char* rowH = g_Aimg + bx * AIMG_SZ + rl * LDB + h * 64;
        char* rowL = rowH + 128 * LDB;
#pragma unroll
        for (int i = 0; i < 16; ++i) {
            float la, lb;
            u32 hh = hilo_hi2(v[2*i], v[2*i+1], la, lb);
            *(u32*)(rowH + 4*i) = hh;
            *(u32*)(rowL + 4*i) = bf2(la, lb);
        }
    } else {
        // ---- classes -> B image hi/lo + scalars (8 threads per class) ----
        const int cblk = bx - 16;                // 0..31
        const int cl = tid >> 3;                 // local class 0..31
        const int sq = tid & 7;                  // d in [sq*8, +8)
        const int cc = cblk * 32 + cl;
        const bool valid = (cc < C);

        float P[8], A[8];
        if (valid) {
            const float4* pb4 = (const float4*)(p_vals + (size_t)cc * 64 + sq * 8);
            const float4* ab4 = (const float4*)(a_vals + (size_t)cc * 64 + sq * 8);
#pragma unroll
            for (int i = 0; i < 2; ++i) {
                float4 pv = pb4[i], av = ab4[i];
                P[4*i+0]=pv.x; P[4*i+1]=pv.y; P[4*i+2]=pv.z; P[4*i+3]=pv.w;
                A[4*i+0]=av.x; A[4*i+1]=av.y; A[4*i+2]=av.z; A[4*i+3]=av.w;
            }
        } else {
#pragma unroll
            for (int i = 0; i < 8; ++i) { P[i] = 0.f; A[i] = 0.f; }
        }

        float psq = 0.f;
#pragma unroll
        for (int i = 0; i < 8; ++i) psq += P[i] * P[i];
        psq += __shfl_xor_sync(0xffffffffu, psq, 1);
        psq += __shfl_xor_sync(0xffffffffu, psq, 2);
        psq += __shfl_xor_sync(0xffffffffu, psq, 4);

        float pn  = fmaxf(sqrtf(psq), 1e-15f);
        float arg = SQRT_K * pn;
        float t   = tanhf(arg) / arg;            // exp0 factor
        float p2  = t * t * psq;                 // |p_poin|^2
        float fac = 1.f + K_CURV * p2;

        float a2 = 0.f, pad = 0.f;
#pragma unroll
        for (int i = 0; i < 8; ++i) {
            float pp = t * P[i];
            float ap = fac * A[i];
            P[i] = pp; A[i] = ap;
            a2  += ap * ap;
            pad += pp * ap;
        }
        a2  += __shfl_xor_sync(0xffffffffu, a2, 1);
        a2  += __shfl_xor_sync(0xffffffffu, a2, 2);
        a2  += __shfl_xor_sync(0xffffffffu, a2, 4);
        pad += __shfl_xor_sync(0xffffffffu, pad, 1);
        pad += __shfl_xor_sync(0xffffffffu, pad, 2);
        pad += __shfl_xor_sync(0xffffffffu, pad, 4);

        if (sq == 0) {
            float an  = fmaxf(sqrtf(a2), 1e-15f);
            float lam = 2.f / (1.f - K_CURV * p2);
            g_x2[cc] = p2;
            g_pc[cc] = -pad;                     // dot(mp, a_poin)
            g_sc[cc] = lam * an / SQRT_K;        // scale
            g_cf[cc] = 2.f * SQRT_K / an;        // folded consts
        }
        char* base = g_Bimg + cblk * BIMG_SZ;
        char* pH = base + (2*cl)   * LDB + sq * 16;
        char* aH = base + (2*cl+1) * LDB + sq * 16;
#pragma unroll
        for (int i = 0; i < 4; ++i) {
            float la, lb;
            u32 hh = hilo_hi2(P[2*i], P[2*i+1], la, lb);
            *(u32*)(pH + 4*i) = hh;
            *(u32*)(pH + 64 * LDB + 4*i) = bf2(la, lb);
            hh = hilo_hi2(A[2*i], A[2*i+1], la, lb);
            *(u32*)(aH + 4*i) = hh;
            *(u32*)(aH + 64 * LDB + 4*i) = bf2(la, lb);
        }
    }
}

// ===================== main: copy images -> HMMA -> epilogue ====================
__global__ void __launch_bounds__(256, 3)
hmlr_hmma(float* __restrict__ out, int B, int C) {
    extern __shared__ __align__(16) char sm[];
    float* s_x2 = (float*)(sm + SB_X2);
    float* s_pc = (float*)(sm + SB_PC);
    float* s_sc = (float*)(sm + SB_SC);
    float* s_cf = (float*)(sm + SB_CF);
    float* s_y2 = (float*)(sm + SB_Y2);
    const u32 sb = smem_u32(sm);

    const int tid   = threadIdx.x;
    const int lane  = tid & 31;
    const int w     = tid >> 5;
    const int cBase = blockIdx.x * 32;
    const int bBase = blockIdx.y * 128;

    // ---- fill: straight vector copies of prebuilt images (L2-hot) ----
    {
        const float4* gA = (const float4*)(g_Aimg + blockIdx.y * AIMG_SZ);
        float4*       sA = (float4*)(sm + SB_AH);
#pragma unroll
        for (int i = 0; i < 9; ++i)                       // 2304 float4s
            sA[tid + i * 256] = gA[tid + i * 256];
        const float4* gB = (const float4*)(g_Bimg + blockIdx.x * BIMG_SZ);
        float4*       sB = (float4*)(sm + SB_BH);
#pragma unroll
        for (int i = 0; i < 4; ++i)                       // 1024 of 1152
            sB[tid + i * 256] = gB[tid + i * 256];
        if (tid < 128) sB[tid + 1024] = gB[tid + 1024];   // remaining 128
        if (tid < 128) s_y2[tid] = g_y2[bBase + tid];
        if (tid >= 128 && tid < 160) {
            int j = tid - 128;
            s_x2[j] = g_x2[cBase + j];
            s_pc[j] = g_pc[cBase + j];
            s_sc[j] = g_sc[cBase + j];
            s_cf[j] = g_cf[cBase + j];
        }
    }
    __syncthreads();

    // ---- HMMA mainloop: warp tile 32m x 32n, K=64 ----
    const int m0  = (w & 3) * 32;
    const int n0r = (w >> 2) * 32;               // B row offset (32 rows = 16 classes)
    const int l16 = lane & 15;

    const u32 aoff0 = (u32)((m0      + l16) * LDB + (lane >> 4) * 16);
    const u32 aoff1 = (u32)((m0 + 16 + l16) * LDB + (lane >> 4) * 16);
    // B x4: lanes 0-7 rows n..n+7 (k0-15), 8-15 same rows +16B, 16-31 rows +8
    const u32 boff  = (u32)((n0r + (lane & 7) + ((lane >> 4) << 3)) * LDB
                            + ((lane >> 3) & 1) * 16);

    float acc[2][4][4];
#pragma unroll
    for (int ma = 0; ma < 2; ++ma)
#pragma unroll
        for (int nb = 0; nb < 4; ++nb)
#pragma unroll
            for (int q = 0; q < 4; ++q) acc[ma][nb][q] = 0.f;

#pragma unroll
    for (int kk = 0; kk < 4; ++kk) {
        const u32 kb = kk * 32;
        u32 ah0[4], ah1[4], al0[4], al1[4];
        ldm_x4(ah0, sb + SB_AH + aoff0 + kb);
        ldm_x4(ah1, sb + SB_AH + aoff1 + kb);
        ldm_x4(al0, sb + SB_AL + aoff0 + kb);
        ldm_x4(al1, sb + SB_AL + aoff1 + kb);
#pragma unroll
        for (int np = 0; np < 2; ++np) {          // 16 B-rows per x4
            u32 bh[4], bl[4];
            ldm_x4(bh, sb + SB_BH + boff + np * (16 * LDB) + kb);
            ldm_x4(bl, sb + SB_BL + boff + np * (16 * LDB) + kb);
#pragma unroll
            for (int s2 = 0; s2 < 2; ++s2) {
                const int nb = np * 2 + s2;
                mma16816(acc[0][nb], ah0, bh + 2*s2);
                mma16816(acc[1][nb], ah1, bh + 2*s2);
                mma16816(acc[0][nb], al0, bh + 2*s2);
                mma16816(acc[1][nb], al1, bh + 2*s2);
                mma16816(acc[0][nb], ah0, bl + 2*s2);
                mma16816(acc[1][nb], ah1, bl + 2*s2);
            }
        }
    }

    // ---- epilogue: register-local (dotp, dota) pairs ----
    const int tg  = lane & 3;
    const int gid = lane >> 2;
#pragma unroll
    for (int nb = 0; nb < 4; ++nb) {
        const int cl = (n0r >> 1) + nb * 4 + tg; // local class 0..31
        const int cg = cBase + cl;
        const float x2c = s_x2[cl];
        const float pcc = s_pc[cl];
        const float scc = s_sc[cl];
        const float cfc = s_cf[cl];
        const float Bf  = 1.f - K_CURV * x2c;
#pragma unroll
        for (int ma = 0; ma < 2; ++ma) {
#pragma unroll
            for (int h = 0; h < 2; ++h) {
                const int m  = m0 + ma * 16 + gid + h * 8;
                const float y2 = s_y2[m];
                const float dotp = acc[ma][nb][2*h];
                const float dota = acc[ma][nb][2*h+1];
                float xy   = -dotp;
                float base = fmaf(2.f * K_CURV, xy, 1.f);
                float Af   = fmaf(K_CURV, y2, base);
                float den  = fmaf((K_CURV * K_CURV) * x2c, y2, base);
                float dotnum = fmaf(Af, pcc, Bf * dota);
                float num  = fmaf(Af, fmaf(Af, x2c, 2.f * Bf * xy), Bf * Bf * y2);
                float wv   = fmaf(den, den, -K_CURV * num);
                float ratio = cfc * dotnum * den * rcp_a(wv);
                float tt = fabsf(ratio);
                float z  = lg2_a(tt + sqrt_a(fmaf(tt, tt, 1.f))) * 0.69314718056f;
                float rv = scc * copysignf(z, ratio);
                if (cg < C) out[(size_t)(bBase + m) * C + cg] = rv;
            }
        }
    }
}

// ===================== launch ==================================================
extern "C" void kernel_launch(void* const* d_in, const int* in_sizes, int n_in,
                              void* d_out, int out_size) {
    const float* x = (const float*)d_in[0];
    const float* a = (const float*)d_in[1];
    const float* p = (const float*)d_in[2];
    float* out = (float*)d_out;
    const int B = in_sizes[0] / 64;   // 2048
    const int C = in_sizes[1] / 64;   // 1000

    hmlr_prep<<<48, 256>>>(x, a, p, B, C);

    cudaFuncSetAttribute(hmlr_hmma, cudaFuncAttributeMaxDynamicSharedMemorySize, SB_TOTAL);
    dim3 grid(32, 16);                 // 512 CTAs, 3/SM
    hmlr_hmma<<<grid, 256, SB_TOTAL>>>(out, B, C);
}